// round 6
// baseline (speedup 1.0000x reference)
#include <cuda_runtime.h>

#define NN 50000
#define NE 800000
#define H_STEP 0.1f

// ---------------- scratch (device globals; no allocation allowed) ----------
static __device__ float4 g_xn[NN * 16];      // node state [n][64], node-major
static __device__ float4 g_y[NN * 16];       // y = KN[i] @ xn, [n][64]
static __device__ float4 g_div[NN * 16];     // scatter accumulator [n][64]
static __device__ float4 g_coords[NN];       // coords [n][3] (+pad)
static __device__ float  g_w[NE];            // edge weights
static __device__ double g_sum[64];
static __device__ double g_sumsq[64];

__device__ __forceinline__ void red_add_v4(float4* addr, float4 v) {
    asm volatile("red.global.add.v4.f32 [%0], {%1,%2,%3,%4};"
                 :: "l"(addr), "f"(v.x), "f"(v.y), "f"(v.z), "f"(v.w)
                 : "memory");
}

// ---------------- N0: open projection + coords/XX0 + y(layer0) + zero div --
__global__ __launch_bounds__(128) void k_n0(
    const float* __restrict__ xn_in,      // [16][NN]
    const float* __restrict__ KNopen,     // [64][16]
    const float* __restrict__ KNclose,    // [3][64]
    const float* __restrict__ KN,         // [3][64][64]
    float* __restrict__ out_xx0)          // XX[0]: [3][NN]
{
    __shared__ float sOpenT[16 * 64];   // [f][o]
    __shared__ float sKN0T[64 * 64];    // [f][o]
    __shared__ float sCloseT[64 * 4];
    int t = threadIdx.x;
    for (int idx = t; idx < 16 * 64; idx += 128) {
        int o = idx / 16, f = idx % 16;
        sOpenT[f * 64 + o] = KNopen[idx];
    }
    for (int idx = t; idx < 64 * 64; idx += 128) {
        int o = idx / 64, f = idx % 64;
        sKN0T[f * 64 + o] = KN[idx];            // KN[0]
    }
    for (int idx = t; idx < 64 * 4; idx += 128) {
        int f = idx / 4, c = idx % 4;
        sCloseT[idx] = (c < 3) ? KNclose[c * 64 + f] : 0.f;
    }
    if (blockIdx.x == 0 && t < 64) { g_sum[t] = 0.0; g_sumsq[t] = 0.0; }
    __syncthreads();

    int n = blockIdx.x * 128 + t;
    if (n >= NN) return;

    float x[64];
#pragma unroll
    for (int o = 0; o < 64; o++) x[o] = 0.f;
#pragma unroll
    for (int f = 0; f < 16; f++) {
        float xf = xn_in[f * NN + n];
#pragma unroll
        for (int o = 0; o < 64; o += 4) {
            float4 k = *(const float4*)&sOpenT[f * 64 + o];
            x[o]     += k.x * xf;
            x[o + 1] += k.y * xf;
            x[o + 2] += k.z * xf;
            x[o + 3] += k.w * xf;
        }
    }
    float4* xnrow  = &g_xn[n * 16];
    float4* divrow = &g_div[n * 16];
#pragma unroll
    for (int q = 0; q < 16; q++) {
        xnrow[q]  = make_float4(x[4 * q], x[4 * q + 1], x[4 * q + 2], x[4 * q + 3]);
        divrow[q] = make_float4(0.f, 0.f, 0.f, 0.f);
    }
    float c0 = 0.f, c1 = 0.f, c2 = 0.f;
#pragma unroll
    for (int f = 0; f < 64; f++) {
        float4 kc = *(const float4*)&sCloseT[f * 4];
        c0 += kc.x * x[f]; c1 += kc.y * x[f]; c2 += kc.z * x[f];
    }
    g_coords[n] = make_float4(c0, c1, c2, 0.f);
    out_xx0[0 * NN + n] = c0;
    out_xx0[1 * NN + n] = c1;
    out_xx0[2 * NN + n] = c2;
    // y = KN[0] @ x  (chunked outputs)
#pragma unroll
    for (int oc = 0; oc < 4; oc++) {
        float acc[16];
#pragma unroll
        for (int q = 0; q < 16; q++) acc[q] = 0.f;
#pragma unroll
        for (int f = 0; f < 64; f++) {
            float xf = x[f];
#pragma unroll
            for (int q = 0; q < 16; q += 4) {
                float4 k = *(const float4*)&sKN0T[f * 64 + oc * 16 + q];
                acc[q]     += k.x * xf;
                acc[q + 1] += k.y * xf;
                acc[q + 2] += k.z * xf;
                acc[q + 3] += k.w * xf;
            }
        }
        float4* yrow = &g_y[n * 16 + oc * 4];
#pragma unroll
        for (int q = 0; q < 4; q++)
            yrow[q] = make_float4(acc[4 * q], acc[4 * q + 1], acc[4 * q + 2], acc[4 * q + 3]);
    }
}

// ---------------- E1: w + stats of a = w*(y_i - y_j) -----------------------
__global__ __launch_bounds__(256) void k_e1(
    const int* __restrict__ iInd, const int* __restrict__ jInd)
{
    __shared__ float sSum[64], sSq[64];
    int t = threadIdx.x;
    if (t < 64) { sSum[t] = 0.f; sSq[t] = 0.f; }
    __syncthreads();

    int lane   = t & 15;
    int group  = blockIdx.x * 16 + (t >> 4);
    int stride = gridDim.x * 16;
    float s0 = 0.f, s1 = 0.f, s2 = 0.f, s3 = 0.f;
    float q0 = 0.f, q1 = 0.f, q2 = 0.f, q3 = 0.f;

    for (int e = group; e < NE; e += stride) {
        int i = iInd[e], j = jInd[e];
        float4 ci = g_coords[i], cj = g_coords[j];
        float dx = ci.x - cj.x, dy = ci.y - cj.y, dz = ci.z - cj.z;
        float w = __expf(-10.f * (dx * dx + dy * dy + dz * dz));
        if (lane == 0) g_w[e] = w;
        float4 yi = g_y[i * 16 + lane];
        float4 yj = g_y[j * 16 + lane];
        float4 a = make_float4(w * (yi.x - yj.x), w * (yi.y - yj.y),
                               w * (yi.z - yj.z), w * (yi.w - yj.w));
        s0 += a.x; s1 += a.y; s2 += a.z; s3 += a.w;
        q0 += a.x * a.x; q1 += a.y * a.y; q2 += a.z * a.z; q3 += a.w * a.w;
    }
    int c = lane * 4;
    atomicAdd(&sSum[c], s0);     atomicAdd(&sSum[c + 1], s1);
    atomicAdd(&sSum[c + 2], s2); atomicAdd(&sSum[c + 3], s3);
    atomicAdd(&sSq[c], q0);      atomicAdd(&sSq[c + 1], q1);
    atomicAdd(&sSq[c + 2], q2);  atomicAdd(&sSq[c + 3], q3);
    __syncthreads();
    if (t < 64)       atomicAdd(&g_sum[t], (double)sSum[t]);
    else if (t < 128) atomicAdd(&g_sumsq[t - 64], (double)sSq[t - 64]);
}

// ---------------- E2 (layers 0,1): recompute a, normalize+relu, scatter ----
__global__ __launch_bounds__(256) void k_e2(
    const int* __restrict__ iInd, const int* __restrict__ jInd)
{
    int t    = threadIdx.x;
    int lane = t & 15;
    int c    = lane * 4;

    float mean[4], inv[4];
    const double invE = 1.0 / (double)NE;
#pragma unroll
    for (int d = 0; d < 4; d++) {
        double s  = g_sum[c + d];
        double sq = g_sumsq[c + d];
        double mu = s * invE;
        double var = sq * invE - mu * mu;
        mean[d] = (float)mu;
        inv[d]  = rsqrtf((float)var + 1e-5f);
    }

    int group  = blockIdx.x * 16 + (t >> 4);
    int stride = gridDim.x * 16;
    for (int e = group; e < NE; e += stride) {
        int i = iInd[e], j = jInd[e];
        float w = g_w[e];
        float4 yi = g_y[i * 16 + lane];
        float4 yj = g_y[j * 16 + lane];
        float4 a = make_float4(w * (yi.x - yj.x), w * (yi.y - yj.y),
                               w * (yi.z - yj.z), w * (yi.w - yj.w));
        float4 x;
        x.x = fmaxf(0.f, (a.x - mean[0]) * inv[0]);
        x.y = fmaxf(0.f, (a.y - mean[1]) * inv[1]);
        x.z = fmaxf(0.f, (a.z - mean[2]) * inv[2]);
        x.w = fmaxf(0.f, (a.w - mean[3]) * inv[3]);
        float4 wg = make_float4(w * x.x, w * x.y, w * x.z, w * x.w);
        red_add_v4(&g_div[i * 16 + lane], wg);
        red_add_v4(&g_div[j * 16 + lane],
                   make_float4(-wg.x, -wg.y, -wg.z, -wg.w));
    }
}

// ---------------- E2 last layer: thread-per-edge + fused xe_out ------------
__global__ __launch_bounds__(256) void k_e2_last(
    const int* __restrict__ iInd, const int* __restrict__ jInd,
    const float* __restrict__ KEclose,     // [16][64]
    float* __restrict__ out_xe)            // [16][NE]
{
    __shared__ float sKT[64 * 16];   // [c][k]
    __shared__ float sMean[64], sInv[64];
    int t = threadIdx.x;
    for (int idx = t; idx < 1024; idx += 256) {
        int k = idx / 64, c = idx % 64;
        sKT[c * 16 + k] = KEclose[idx];
    }
    if (t < 64) {
        const double invE = 1.0 / (double)NE;
        double s  = g_sum[t];
        double sq = g_sumsq[t];
        double mu = s * invE;
        double var = sq * invE - mu * mu;
        sMean[t] = (float)mu;
        sInv[t]  = rsqrtf((float)var + 1e-5f);
    }
    __syncthreads();

    int e = blockIdx.x * 256 + t;
    if (e >= NE) return;
    int i = iInd[e], j = jInd[e];
    float w = g_w[e];

    float acc[16];
#pragma unroll
    for (int k = 0; k < 16; k++) acc[k] = 0.f;

#pragma unroll
    for (int q = 0; q < 16; q++) {
        float4 yi = g_y[i * 16 + q];
        float4 yj = g_y[j * 16 + q];
        float4 mn = *(const float4*)&sMean[4 * q];
        float4 iv = *(const float4*)&sInv[4 * q];
        float4 x;
        x.x = fmaxf(0.f, (w * (yi.x - yj.x) - mn.x) * iv.x);
        x.y = fmaxf(0.f, (w * (yi.y - yj.y) - mn.y) * iv.y);
        x.z = fmaxf(0.f, (w * (yi.z - yj.z) - mn.z) * iv.z);
        x.w = fmaxf(0.f, (w * (yi.w - yj.w) - mn.w) * iv.w);
        float4 wg = make_float4(w * x.x, w * x.y, w * x.z, w * x.w);
        red_add_v4(&g_div[i * 16 + q], wg);
        red_add_v4(&g_div[j * 16 + q],
                   make_float4(-wg.x, -wg.y, -wg.z, -wg.w));
        float xs[4] = {x.x, x.y, x.z, x.w};
#pragma unroll
        for (int dd = 0; dd < 4; dd++) {
            float xc = xs[dd];
            int c = 4 * q + dd;
#pragma unroll
            for (int kq = 0; kq < 4; kq++) {
                float4 kk = *(const float4*)&sKT[c * 16 + kq * 4];
                acc[kq * 4]     += kk.x * xc;
                acc[kq * 4 + 1] += kk.y * xc;
                acc[kq * 4 + 2] += kk.z * xc;
                acc[kq * 4 + 3] += kk.w * xc;
            }
        }
    }
#pragma unroll
    for (int k = 0; k < 16; k++) out_xe[k * NE + e] = acc[k];
}

// ---------------- Node update: 2 nodes x 32 channels per thread ------------
// 128 threads, 128 nodes/block. Thread (nl = t>>1, h = t&1) handles nodes
// base+nl and base+nl+64, channels [32h, 32h+32). Partner channel half lives
// in lane t^1's registers; exchanged via __shfl_xor. Smem = 33KB.
__global__ void __launch_bounds__(128) k_node(
    const float* __restrict__ KNi,     // KN[i] [e][c]
    const float* __restrict__ KNnext,  // KN[i+1] or nullptr
    const float* __restrict__ KNclose,
    float* __restrict__ out_xx,        // XX[i+1]: [3][NN]
    float* __restrict__ out_xn,        // final xn out or nullptr
    int zero_sums)
{
    __shared__ float sK[64 * 64];     // [e][c]
    __shared__ float sKnT[64 * 64];   // [f][o]
    __shared__ float sCloseT[64 * 4];
    int t = threadIdx.x;
    for (int idx = t; idx < 4096; idx += 128) sK[idx] = KNi[idx];
    if (KNnext) {
        for (int idx = t; idx < 4096; idx += 128) {
            int o = idx / 64, f = idx % 64;
            sKnT[f * 64 + o] = KNnext[idx];
        }
    }
    for (int idx = t; idx < 256; idx += 128) {
        int f = idx / 4, cc = idx % 4;
        sCloseT[idx] = (cc < 3) ? KNclose[cc * 64 + f] : 0.f;
    }
    if (zero_sums && blockIdx.x == 0 && t < 64) { g_sum[t] = 0.0; g_sumsq[t] = 0.0; }
    __syncthreads();

    int nl = t >> 1, h = t & 1;
    int cb = 32 * h;
    int nA = blockIdx.x * 128 + nl;
    int nB = nA + 64;
    bool vA = nA < NN, vB = nB < NN;
    const float4 z4 = make_float4(0.f, 0.f, 0.f, 0.f);

    // ---- update matvec: acc[c] = sum_e K[e][c] * d[e], 2 nodes ----
    float accA[32], accB[32];
#pragma unroll
    for (int c = 0; c < 32; c++) { accA[c] = 0.f; accB[c] = 0.f; }
#pragma unroll
    for (int q = 0; q < 16; q++) {
        float4 dvA = vA ? g_div[(size_t)nA * 16 + q] : z4;
        float4 dvB = vB ? g_div[(size_t)nB * 16 + q] : z4;
        float dsA[4] = {dvA.x, dvA.y, dvA.z, dvA.w};
        float dsB[4] = {dvB.x, dvB.y, dvB.z, dvB.w};
#pragma unroll
        for (int ee = 0; ee < 4; ee++) {
            float deA = dsA[ee], deB = dsB[ee];
            const float* krow = &sK[(4 * q + ee) * 64 + cb];
#pragma unroll
            for (int c = 0; c < 32; c += 4) {
                float4 k = *(const float4*)&krow[c];
                accA[c]     += k.x * deA;  accB[c]     += k.x * deB;
                accA[c + 1] += k.y * deA;  accB[c + 1] += k.y * deB;
                accA[c + 2] += k.z * deA;  accB[c + 2] += k.z * deB;
                accA[c + 3] += k.w * deA;  accB[c + 3] += k.w * deB;
            }
        }
    }
    // zero div for next layer; rows only read by own lane pair (same warp)
    __syncwarp();
#pragma unroll
    for (int q = 0; q < 8; q++) {
        if (vA) g_div[(size_t)nA * 16 + 8 * h + q] = z4;
        if (vB) g_div[(size_t)nB * 16 + 8 * h + q] = z4;
    }

    // ---- x = xn - H*acc (reuse acc regs as x); write back ----
    if (vA) {
#pragma unroll
        for (int q = 0; q < 8; q++) {
            float4 xv = g_xn[(size_t)nA * 16 + 8 * h + q];
            accA[4 * q]     = xv.x - H_STEP * accA[4 * q];
            accA[4 * q + 1] = xv.y - H_STEP * accA[4 * q + 1];
            accA[4 * q + 2] = xv.z - H_STEP * accA[4 * q + 2];
            accA[4 * q + 3] = xv.w - H_STEP * accA[4 * q + 3];
            g_xn[(size_t)nA * 16 + 8 * h + q] =
                make_float4(accA[4 * q], accA[4 * q + 1],
                            accA[4 * q + 2], accA[4 * q + 3]);
        }
    }
    if (vB) {
#pragma unroll
        for (int q = 0; q < 8; q++) {
            float4 xv = g_xn[(size_t)nB * 16 + 8 * h + q];
            accB[4 * q]     = xv.x - H_STEP * accB[4 * q];
            accB[4 * q + 1] = xv.y - H_STEP * accB[4 * q + 1];
            accB[4 * q + 2] = xv.z - H_STEP * accB[4 * q + 2];
            accB[4 * q + 3] = xv.w - H_STEP * accB[4 * q + 3];
            g_xn[(size_t)nB * 16 + 8 * h + q] =
                make_float4(accB[4 * q], accB[4 * q + 1],
                            accB[4 * q + 2], accB[4 * q + 3]);
        }
    }

    // ---- coords: partial over own 32 channels, partner half via shfl ----
    {
        float cA0 = 0.f, cA1 = 0.f, cA2 = 0.f;
        float cB0 = 0.f, cB1 = 0.f, cB2 = 0.f;
#pragma unroll
        for (int fl = 0; fl < 32; fl++) {
            float4 kc = *(const float4*)&sCloseT[(cb + fl) * 4];
            cA0 += kc.x * accA[fl]; cA1 += kc.y * accA[fl]; cA2 += kc.z * accA[fl];
            cB0 += kc.x * accB[fl]; cB1 += kc.y * accB[fl]; cB2 += kc.z * accB[fl];
        }
        float pA0 = __shfl_xor_sync(0xFFFFFFFFu, cA0, 1);
        float pA1 = __shfl_xor_sync(0xFFFFFFFFu, cA1, 1);
        float pA2 = __shfl_xor_sync(0xFFFFFFFFu, cA2, 1);
        float pB0 = __shfl_xor_sync(0xFFFFFFFFu, cB0, 1);
        float pB1 = __shfl_xor_sync(0xFFFFFFFFu, cB1, 1);
        float pB2 = __shfl_xor_sync(0xFFFFFFFFu, cB2, 1);
        if (h == 0) {
            if (vA) {
                float c0 = cA0 + pA0, c1 = cA1 + pA1, c2 = cA2 + pA2;
                g_coords[nA] = make_float4(c0, c1, c2, 0.f);
                out_xx[0 * NN + nA] = c0;
                out_xx[1 * NN + nA] = c1;
                out_xx[2 * NN + nA] = c2;
                if (out_xn) {
                    out_xn[0 * NN + nA] = c0;
                    out_xn[1 * NN + nA] = c1;
                    out_xn[2 * NN + nA] = c2;
                }
            }
            if (vB) {
                float c0 = cB0 + pB0, c1 = cB1 + pB1, c2 = cB2 + pB2;
                g_coords[nB] = make_float4(c0, c1, c2, 0.f);
                out_xx[0 * NN + nB] = c0;
                out_xx[1 * NN + nB] = c1;
                out_xx[2 * NN + nB] = c2;
                if (out_xn) {
                    out_xn[0 * NN + nB] = c0;
                    out_xn[1 * NN + nB] = c1;
                    out_xn[2 * NN + nB] = c2;
                }
            }
        }
    }

    // ---- y = KNnext @ x (own 32 outputs, both nodes) ----
    if (KNnext) {
        float yA[32], yB[32];
#pragma unroll
        for (int c = 0; c < 32; c++) { yA[c] = 0.f; yB[c] = 0.f; }
#pragma unroll
        for (int fl = 0; fl < 32; fl++) {
            float aOwn = accA[fl];
            float bOwn = accB[fl];
            float aPar = __shfl_xor_sync(0xFFFFFFFFu, aOwn, 1);
            float bPar = __shfl_xor_sync(0xFFFFFFFFu, bOwn, 1);
            float aLo = h ? aPar : aOwn;
            float aHi = h ? aOwn : aPar;
            float bLo = h ? bPar : bOwn;
            float bHi = h ? bOwn : bPar;
            const float* kLo = &sKnT[fl * 64 + cb];
            const float* kHi = &sKnT[(32 + fl) * 64 + cb];
#pragma unroll
            for (int c = 0; c < 32; c += 4) {
                float4 kl = *(const float4*)&kLo[c];
                float4 kh = *(const float4*)&kHi[c];
                yA[c]     += kl.x * aLo + kh.x * aHi;
                yA[c + 1] += kl.y * aLo + kh.y * aHi;
                yA[c + 2] += kl.z * aLo + kh.z * aHi;
                yA[c + 3] += kl.w * aLo + kh.w * aHi;
                yB[c]     += kl.x * bLo + kh.x * bHi;
                yB[c + 1] += kl.y * bLo + kh.y * bHi;
                yB[c + 2] += kl.z * bLo + kh.z * bHi;
                yB[c + 3] += kl.w * bLo + kh.w * bHi;
            }
        }
        if (vA) {
#pragma unroll
            for (int q = 0; q < 8; q++)
                g_y[(size_t)nA * 16 + 8 * h + q] =
                    make_float4(yA[4 * q], yA[4 * q + 1],
                                yA[4 * q + 2], yA[4 * q + 3]);
        }
        if (vB) {
#pragma unroll
            for (int q = 0; q < 8; q++)
                g_y[(size_t)nB * 16 + 8 * h + q] =
                    make_float4(yB[4 * q], yB[4 * q + 1],
                                yB[4 * q + 2], yB[4 * q + 3]);
        }
    }
}

// ---------------- launcher -------------------------------------------------
extern "C" void kernel_launch(void* const* d_in, const int* in_sizes, int n_in,
                              void* d_out, int out_size)
{
    const float* xn_in   = (const float*)d_in[0];
    // d_in[1] = xe input: dead (overwritten before first read in reference)
    const int*   iInd    = (const int*)d_in[2];
    const int*   jInd    = (const int*)d_in[3];
    const float* KNopen  = (const float*)d_in[4];
    // d_in[5] = KEopen: dead
    const float* KNclose = (const float*)d_in[6];
    const float* KEclose = (const float*)d_in[7];
    const float* KN      = (const float*)d_in[8];

    float* out    = (float*)d_out;
    float* out_xn = out;                       // [3][NN]
    float* out_xe = out + 3 * NN;              // [16][NE]
    float* out_XX = out + 3 * NN + 16 * NE;    // [4][3][NN]

    int nb_n  = (NN + 127) / 128;
    int nb_el = (NE + 255) / 256;
    const int GE = 1184;

    k_n0<<<nb_n, 128>>>(xn_in, KNopen, KNclose, KN, out_XX);
    for (int i = 0; i < 3; i++) {
        k_e1<<<GE, 256>>>(iInd, jInd);
        if (i < 2) k_e2<<<GE, 256>>>(iInd, jInd);
        else       k_e2_last<<<nb_el, 256>>>(iInd, jInd, KEclose, out_xe);
        const float* KNi = KN + i * 4096;
        const float* KNn = (i < 2) ? (KN + (i + 1) * 4096) : nullptr;
        float* xx  = out_XX + (size_t)(i + 1) * 3 * NN;
        float* oxn = (i == 2) ? out_xn : nullptr;
        k_node<<<nb_n, 128>>>(KNi, KNn, KNclose, xx, oxn, (i < 2) ? 1 : 0);
    }
}

// round 9
// speedup vs baseline: 1.0430x; 1.0430x over previous
#include <cuda_runtime.h>

#define NN 50000
#define NE 800000
#define H_STEP 0.1f

// ---------------- scratch (device globals; no allocation allowed) ----------
static __device__ float4 g_xn[NN * 16];      // node state [n][64], node-major
static __device__ float4 g_y[NN * 16];       // y = KN[i] @ xn, [n][64]
static __device__ float4 g_div[NN * 16];     // scatter accumulator [n][64]
static __device__ float4 g_coords[NN];       // coords [n][3] (+pad)
static __device__ float  g_w[NE];            // edge weights
static __device__ double g_sum[64];
static __device__ double g_sumsq[64];

__device__ __forceinline__ void red_add_v4(float4* addr, float4 v) {
    asm volatile("red.global.add.v4.f32 [%0], {%1,%2,%3,%4};"
                 :: "l"(addr), "f"(v.x), "f"(v.y), "f"(v.z), "f"(v.w)
                 : "memory");
}

// ---------------- N0: open projection + coords/XX0 + y(layer0) + zero div --
__global__ __launch_bounds__(128) void k_n0(
    const float* __restrict__ xn_in,      // [16][NN]
    const float* __restrict__ KNopen,     // [64][16]
    const float* __restrict__ KNclose,    // [3][64]
    const float* __restrict__ KN,         // [3][64][64]
    float* __restrict__ out_xx0)          // XX[0]: [3][NN]
{
    __shared__ float sOpenT[16 * 64];   // [f][o]
    __shared__ float sKN0T[64 * 64];    // [f][o]
    __shared__ float sCloseT[64 * 4];
    int t = threadIdx.x;
    for (int idx = t; idx < 16 * 64; idx += 128) {
        int o = idx / 16, f = idx % 16;
        sOpenT[f * 64 + o] = KNopen[idx];
    }
    for (int idx = t; idx < 64 * 64; idx += 128) {
        int o = idx / 64, f = idx % 64;
        sKN0T[f * 64 + o] = KN[idx];            // KN[0]
    }
    for (int idx = t; idx < 64 * 4; idx += 128) {
        int f = idx / 4, c = idx % 4;
        sCloseT[idx] = (c < 3) ? KNclose[c * 64 + f] : 0.f;
    }
    if (blockIdx.x == 0 && t < 64) { g_sum[t] = 0.0; g_sumsq[t] = 0.0; }
    __syncthreads();

    int n = blockIdx.x * 128 + t;
    if (n >= NN) return;

    float x[64];
#pragma unroll
    for (int o = 0; o < 64; o++) x[o] = 0.f;
#pragma unroll
    for (int f = 0; f < 16; f++) {
        float xf = xn_in[f * NN + n];
#pragma unroll
        for (int o = 0; o < 64; o += 4) {
            float4 k = *(const float4*)&sOpenT[f * 64 + o];
            x[o]     += k.x * xf;
            x[o + 1] += k.y * xf;
            x[o + 2] += k.z * xf;
            x[o + 3] += k.w * xf;
        }
    }
    float4* xnrow  = &g_xn[n * 16];
    float4* divrow = &g_div[n * 16];
#pragma unroll
    for (int q = 0; q < 16; q++) {
        xnrow[q]  = make_float4(x[4 * q], x[4 * q + 1], x[4 * q + 2], x[4 * q + 3]);
        divrow[q] = make_float4(0.f, 0.f, 0.f, 0.f);
    }
    float c0 = 0.f, c1 = 0.f, c2 = 0.f;
#pragma unroll
    for (int f = 0; f < 64; f++) {
        float4 kc = *(const float4*)&sCloseT[f * 4];
        c0 += kc.x * x[f]; c1 += kc.y * x[f]; c2 += kc.z * x[f];
    }
    g_coords[n] = make_float4(c0, c1, c2, 0.f);
    out_xx0[0 * NN + n] = c0;
    out_xx0[1 * NN + n] = c1;
    out_xx0[2 * NN + n] = c2;
    // y = KN[0] @ x  (chunked outputs)
#pragma unroll
    for (int oc = 0; oc < 4; oc++) {
        float acc[16];
#pragma unroll
        for (int q = 0; q < 16; q++) acc[q] = 0.f;
#pragma unroll
        for (int f = 0; f < 64; f++) {
            float xf = x[f];
#pragma unroll
            for (int q = 0; q < 16; q += 4) {
                float4 k = *(const float4*)&sKN0T[f * 64 + oc * 16 + q];
                acc[q]     += k.x * xf;
                acc[q + 1] += k.y * xf;
                acc[q + 2] += k.z * xf;
                acc[q + 3] += k.w * xf;
            }
        }
        float4* yrow = &g_y[n * 16 + oc * 4];
#pragma unroll
        for (int q = 0; q < 4; q++)
            yrow[q] = make_float4(acc[4 * q], acc[4 * q + 1], acc[4 * q + 2], acc[4 * q + 3]);
    }
}

// ---------------- E1: w + stats of a = w*(y_i - y_j) -----------------------
__global__ __launch_bounds__(256) void k_e1(
    const int* __restrict__ iInd, const int* __restrict__ jInd)
{
    __shared__ float sSum[64], sSq[64];
    int t = threadIdx.x;
    if (t < 64) { sSum[t] = 0.f; sSq[t] = 0.f; }
    __syncthreads();

    int lane   = t & 15;
    int group  = blockIdx.x * 16 + (t >> 4);
    int stride = gridDim.x * 16;
    float s0 = 0.f, s1 = 0.f, s2 = 0.f, s3 = 0.f;
    float q0 = 0.f, q1 = 0.f, q2 = 0.f, q3 = 0.f;

    for (int e = group; e < NE; e += stride) {
        int i = iInd[e], j = jInd[e];
        float4 ci = g_coords[i], cj = g_coords[j];
        float dx = ci.x - cj.x, dy = ci.y - cj.y, dz = ci.z - cj.z;
        float w = __expf(-10.f * (dx * dx + dy * dy + dz * dz));
        if (lane == 0) g_w[e] = w;
        float4 yi = g_y[i * 16 + lane];
        float4 yj = g_y[j * 16 + lane];
        float4 a = make_float4(w * (yi.x - yj.x), w * (yi.y - yj.y),
                               w * (yi.z - yj.z), w * (yi.w - yj.w));
        s0 += a.x; s1 += a.y; s2 += a.z; s3 += a.w;
        q0 += a.x * a.x; q1 += a.y * a.y; q2 += a.z * a.z; q3 += a.w * a.w;
    }
    int c = lane * 4;
    atomicAdd(&sSum[c], s0);     atomicAdd(&sSum[c + 1], s1);
    atomicAdd(&sSum[c + 2], s2); atomicAdd(&sSum[c + 3], s3);
    atomicAdd(&sSq[c], q0);      atomicAdd(&sSq[c + 1], q1);
    atomicAdd(&sSq[c + 2], q2);  atomicAdd(&sSq[c + 3], q3);
    __syncthreads();
    if (t < 64)       atomicAdd(&g_sum[t], (double)sSum[t]);
    else if (t < 128) atomicAdd(&g_sumsq[t - 64], (double)sSq[t - 64]);
}

// ---------------- E2 (layers 0,1): recompute a, normalize+relu, scatter ----
__global__ __launch_bounds__(256) void k_e2(
    const int* __restrict__ iInd, const int* __restrict__ jInd)
{
    int t    = threadIdx.x;
    int lane = t & 15;
    int c    = lane * 4;

    float mean[4], inv[4];
    const double invE = 1.0 / (double)NE;
#pragma unroll
    for (int d = 0; d < 4; d++) {
        double s  = g_sum[c + d];
        double sq = g_sumsq[c + d];
        double mu = s * invE;
        double var = sq * invE - mu * mu;
        mean[d] = (float)mu;
        inv[d]  = rsqrtf((float)var + 1e-5f);
    }

    int group  = blockIdx.x * 16 + (t >> 4);
    int stride = gridDim.x * 16;
    for (int e = group; e < NE; e += stride) {
        int i = iInd[e], j = jInd[e];
        float w = g_w[e];
        float4 yi = g_y[i * 16 + lane];
        float4 yj = g_y[j * 16 + lane];
        float4 a = make_float4(w * (yi.x - yj.x), w * (yi.y - yj.y),
                               w * (yi.z - yj.z), w * (yi.w - yj.w));
        float4 x;
        x.x = fmaxf(0.f, (a.x - mean[0]) * inv[0]);
        x.y = fmaxf(0.f, (a.y - mean[1]) * inv[1]);
        x.z = fmaxf(0.f, (a.z - mean[2]) * inv[2]);
        x.w = fmaxf(0.f, (a.w - mean[3]) * inv[3]);
        float4 wg = make_float4(w * x.x, w * x.y, w * x.z, w * x.w);
        red_add_v4(&g_div[i * 16 + lane], wg);
        red_add_v4(&g_div[j * 16 + lane],
                   make_float4(-wg.x, -wg.y, -wg.z, -wg.w));
    }
}

// ---------------- E2 last layer: thread-per-edge + fused xe_out ------------
__global__ __launch_bounds__(256) void k_e2_last(
    const int* __restrict__ iInd, const int* __restrict__ jInd,
    const float* __restrict__ KEclose,     // [16][64]
    float* __restrict__ out_xe)            // [16][NE]
{
    __shared__ float sKT[64 * 16];   // [c][k]
    __shared__ float sMean[64], sInv[64];
    int t = threadIdx.x;
    for (int idx = t; idx < 1024; idx += 256) {
        int k = idx / 64, c = idx % 64;
        sKT[c * 16 + k] = KEclose[idx];
    }
    if (t < 64) {
        const double invE = 1.0 / (double)NE;
        double s  = g_sum[t];
        double sq = g_sumsq[t];
        double mu = s * invE;
        double var = sq * invE - mu * mu;
        sMean[t] = (float)mu;
        sInv[t]  = rsqrtf((float)var + 1e-5f);
    }
    __syncthreads();

    int e = blockIdx.x * 256 + t;
    if (e >= NE) return;
    int i = iInd[e], j = jInd[e];
    float w = g_w[e];

    float acc[16];
#pragma unroll
    for (int k = 0; k < 16; k++) acc[k] = 0.f;

#pragma unroll
    for (int q = 0; q < 16; q++) {
        float4 yi = g_y[i * 16 + q];
        float4 yj = g_y[j * 16 + q];
        float4 mn = *(const float4*)&sMean[4 * q];
        float4 iv = *(const float4*)&sInv[4 * q];
        float4 x;
        x.x = fmaxf(0.f, (w * (yi.x - yj.x) - mn.x) * iv.x);
        x.y = fmaxf(0.f, (w * (yi.y - yj.y) - mn.y) * iv.y);
        x.z = fmaxf(0.f, (w * (yi.z - yj.z) - mn.z) * iv.z);
        x.w = fmaxf(0.f, (w * (yi.w - yj.w) - mn.w) * iv.w);
        float4 wg = make_float4(w * x.x, w * x.y, w * x.z, w * x.w);
        red_add_v4(&g_div[i * 16 + q], wg);
        red_add_v4(&g_div[j * 16 + q],
                   make_float4(-wg.x, -wg.y, -wg.z, -wg.w));
        float xs[4] = {x.x, x.y, x.z, x.w};
#pragma unroll
        for (int dd = 0; dd < 4; dd++) {
            float xc = xs[dd];
            int c = 4 * q + dd;
#pragma unroll
            for (int kq = 0; kq < 4; kq++) {
                float4 kk = *(const float4*)&sKT[c * 16 + kq * 4];
                acc[kq * 4]     += kk.x * xc;
                acc[kq * 4 + 1] += kk.y * xc;
                acc[kq * 4 + 2] += kk.z * xc;
                acc[kq * 4 + 3] += kk.w * xc;
            }
        }
    }
#pragma unroll
    for (int k = 0; k < 16; k++) out_xe[k * NE + e] = acc[k];
}

// ---------------- Node update: 2 threads per node, 32 channels each --------
// 256 threads, 128 nodes/block, grid 391 -> 3128 warps (~2x the warps of the
// thread-per-node variant). Thread (nl = t>>1, h = t&1) owns channels
// [32h, 32h+32) of node base+nl for both matvecs. For the y matvec the full
// x row is re-read from g_xn after __syncthreads() (same-block global
// write->sync->read; L1 hit). No shfl, no wide register arrays live across
// phases. FP accumulation order identical to the proven thread-per-node
// version (f ascending) in all matvecs -> bit-identical outputs.
__global__ void __launch_bounds__(256) k_node(
    const float* __restrict__ KNi,     // KN[i] [e][c]
    const float* __restrict__ KNnext,  // KN[i+1] or nullptr
    const float* __restrict__ KNclose,
    float* __restrict__ out_xx,        // XX[i+1]: [3][NN]
    float* __restrict__ out_xn,        // final xn out or nullptr
    int zero_sums)
{
    __shared__ float sK[64 * 64];     // [e][c]
    __shared__ float sKnT[64 * 64];   // [f][o]
    __shared__ float sCloseT[64 * 4];
    int t = threadIdx.x;
    for (int idx = t; idx < 4096; idx += 256) sK[idx] = KNi[idx];
    if (KNnext) {
        for (int idx = t; idx < 4096; idx += 256) {
            int o = idx / 64, f = idx % 64;
            sKnT[f * 64 + o] = KNnext[idx];
        }
    }
    if (t < 256) {
        int f = t / 4, cc = t % 4;
        sCloseT[t] = (cc < 3) ? KNclose[cc * 64 + f] : 0.f;
    }
    if (zero_sums && blockIdx.x == 0 && t < 64) { g_sum[t] = 0.0; g_sumsq[t] = 0.0; }
    __syncthreads();

    int nl = t >> 1, h = t & 1;
    int cb = 32 * h;
    int n  = blockIdx.x * 128 + nl;
    bool v = n < NN;
    const float4 z4 = make_float4(0.f, 0.f, 0.f, 0.f);

    // ---- phase 1: acc[c] = sum_e K[e][c] * d[e] over own 32 channels ----
    float acc[32];
#pragma unroll
    for (int c = 0; c < 32; c++) acc[c] = 0.f;
#pragma unroll
    for (int q = 0; q < 16; q++) {
        float4 dv = v ? g_div[(size_t)n * 16 + q] : z4;
        float ds[4] = {dv.x, dv.y, dv.z, dv.w};
#pragma unroll
        for (int ee = 0; ee < 4; ee++) {
            float de = ds[ee];
            const float* krow = &sK[(4 * q + ee) * 64 + cb];
#pragma unroll
            for (int c = 0; c < 32; c += 4) {
                float4 k = *(const float4*)&krow[c];
                acc[c]     += k.x * de;
                acc[c + 1] += k.y * de;
                acc[c + 2] += k.z * de;
                acc[c + 3] += k.w * de;
            }
        }
    }
    // zero div for next layer. Both threads of the pair (same warp) have
    // finished reading the row; __syncwarp orders reads before these stores.
    __syncwarp();
    if (v) {
#pragma unroll
        for (int q = 0; q < 8; q++)
            g_div[(size_t)n * 16 + 8 * h + q] = z4;
    }

    // ---- x = xn - H*acc for own half; write back to g_xn ----
    if (v) {
#pragma unroll
        for (int q = 0; q < 8; q++) {
            float4 xv = g_xn[(size_t)n * 16 + 8 * h + q];
            xv.x -= H_STEP * acc[4 * q];
            xv.y -= H_STEP * acc[4 * q + 1];
            xv.z -= H_STEP * acc[4 * q + 2];
            xv.w -= H_STEP * acc[4 * q + 3];
            g_xn[(size_t)n * 16 + 8 * h + q] = xv;
        }
    }
    __syncthreads();   // x visible block-wide (same-SM L1)

    // ---- coords: h==0 thread reads the full (fresh) row ----
    if (h == 0 && v) {
        float c0 = 0.f, c1 = 0.f, c2 = 0.f;
#pragma unroll
        for (int q = 0; q < 16; q++) {
            float4 xv = g_xn[(size_t)n * 16 + q];
            float xs[4] = {xv.x, xv.y, xv.z, xv.w};
#pragma unroll
            for (int d = 0; d < 4; d++) {
                float4 kc = *(const float4*)&sCloseT[(4 * q + d) * 4];
                c0 += kc.x * xs[d]; c1 += kc.y * xs[d]; c2 += kc.z * xs[d];
            }
        }
        g_coords[n] = make_float4(c0, c1, c2, 0.f);
        out_xx[0 * NN + n] = c0;
        out_xx[1 * NN + n] = c1;
        out_xx[2 * NN + n] = c2;
        if (out_xn) {
            out_xn[0 * NN + n] = c0;
            out_xn[1 * NN + n] = c1;
            out_xn[2 * NN + n] = c2;
        }
    }

    // ---- y = KNnext @ x: own 32 outputs; full x row streamed from L1 ----
    if (KNnext) {
        float y[32];
#pragma unroll
        for (int c = 0; c < 32; c++) y[c] = 0.f;
#pragma unroll
        for (int q = 0; q < 16; q++) {
            float4 xv = v ? g_xn[(size_t)n * 16 + q] : z4;
            float xs[4] = {xv.x, xv.y, xv.z, xv.w};
#pragma unroll
            for (int d = 0; d < 4; d++) {
                float xf = xs[d];
                const float* kcol = &sKnT[(4 * q + d) * 64 + cb];
#pragma unroll
                for (int c = 0; c < 32; c += 4) {
                    float4 k = *(const float4*)&kcol[c];
                    y[c]     += k.x * xf;
                    y[c + 1] += k.y * xf;
                    y[c + 2] += k.z * xf;
                    y[c + 3] += k.w * xf;
                }
            }
        }
        if (v) {
#pragma unroll
            for (int q = 0; q < 8; q++)
                g_y[(size_t)n * 16 + 8 * h + q] =
                    make_float4(y[4 * q], y[4 * q + 1],
                                y[4 * q + 2], y[4 * q + 3]);
        }
    }
}

// ---------------- launcher -------------------------------------------------
extern "C" void kernel_launch(void* const* d_in, const int* in_sizes, int n_in,
                              void* d_out, int out_size)
{
    const float* xn_in   = (const float*)d_in[0];
    // d_in[1] = xe input: dead (overwritten before first read in reference)
    const int*   iInd    = (const int*)d_in[2];
    const int*   jInd    = (const int*)d_in[3];
    const float* KNopen  = (const float*)d_in[4];
    // d_in[5] = KEopen: dead
    const float* KNclose = (const float*)d_in[6];
    const float* KEclose = (const float*)d_in[7];
    const float* KN      = (const float*)d_in[8];

    float* out    = (float*)d_out;
    float* out_xn = out;                       // [3][NN]
    float* out_xe = out + 3 * NN;              // [16][NE]
    float* out_XX = out + 3 * NN + 16 * NE;    // [4][3][NN]

    int nb_n0 = (NN + 127) / 128;
    int nb_nd = (NN + 127) / 128;   // 128 nodes per 256-thread block
    int nb_el = (NE + 255) / 256;
    const int GE = 1184;

    k_n0<<<nb_n0, 128>>>(xn_in, KNopen, KNclose, KN, out_XX);
    for (int i = 0; i < 3; i++) {
        k_e1<<<GE, 256>>>(iInd, jInd);
        if (i < 2) k_e2<<<GE, 256>>>(iInd, jInd);
        else       k_e2_last<<<nb_el, 256>>>(iInd, jInd, KEclose, out_xe);
        const float* KNi = KN + i * 4096;
        const float* KNn = (i < 2) ? (KN + (i + 1) * 4096) : nullptr;
        float* xx  = out_XX + (size_t)(i + 1) * 3 * NN;
        float* oxn = (i == 2) ? out_xn : nullptr;
        k_node<<<nb_nd, 256>>>(KNi, KNn, KNclose, xx, oxn, (i < 2) ? 1 : 0);
    }
}

// round 10
// speedup vs baseline: 1.1206x; 1.0744x over previous
#include <cuda_runtime.h>

#define NN 50000
#define NE 800000
#define H_STEP 0.1f

// ---------------- scratch (device globals; no allocation allowed) ----------
static __device__ float4 g_xn[NN * 16];      // node state [n][64], node-major
static __device__ float4 g_y[NN * 16];       // y = KN[i] @ xn, [n][64]
static __device__ float4 g_div[NN * 16];     // scatter accumulator [n][64]
static __device__ float4 g_coords[NN];       // coords [n][3] (+pad)
static __device__ float  g_w[NE];            // edge weights
static __device__ double g_sum[64];
static __device__ double g_sumsq[64];

__device__ __forceinline__ void red_add_v4(float4* addr, float4 v) {
    asm volatile("red.global.add.v4.f32 [%0], {%1,%2,%3,%4};"
                 :: "l"(addr), "f"(v.x), "f"(v.y), "f"(v.z), "f"(v.w)
                 : "memory");
}

// ---------------- N0: open projection + coords/XX0 + y(layer0) + zero div --
__global__ __launch_bounds__(128) void k_n0(
    const float* __restrict__ xn_in,      // [16][NN]
    const float* __restrict__ KNopen,     // [64][16]
    const float* __restrict__ KNclose,    // [3][64]
    const float* __restrict__ KN,         // [3][64][64]
    float* __restrict__ out_xx0)          // XX[0]: [3][NN]
{
    __shared__ float sOpenT[16 * 64];   // [f][o]
    __shared__ float sKN0T[64 * 64];    // [f][o]
    __shared__ float sCloseT[64 * 4];
    int t = threadIdx.x;
    for (int idx = t; idx < 16 * 64; idx += 128) {
        int o = idx / 16, f = idx % 16;
        sOpenT[f * 64 + o] = KNopen[idx];
    }
    for (int idx = t; idx < 64 * 64; idx += 128) {
        int o = idx / 64, f = idx % 64;
        sKN0T[f * 64 + o] = KN[idx];            // KN[0]
    }
    for (int idx = t; idx < 64 * 4; idx += 128) {
        int f = idx / 4, c = idx % 4;
        sCloseT[idx] = (c < 3) ? KNclose[c * 64 + f] : 0.f;
    }
    if (blockIdx.x == 0 && t < 64) { g_sum[t] = 0.0; g_sumsq[t] = 0.0; }
    __syncthreads();

    int n = blockIdx.x * 128 + t;
    if (n >= NN) return;

    float x[64];
#pragma unroll
    for (int o = 0; o < 64; o++) x[o] = 0.f;
#pragma unroll
    for (int f = 0; f < 16; f++) {
        float xf = xn_in[f * NN + n];
#pragma unroll
        for (int o = 0; o < 64; o += 4) {
            float4 k = *(const float4*)&sOpenT[f * 64 + o];
            x[o]     += k.x * xf;
            x[o + 1] += k.y * xf;
            x[o + 2] += k.z * xf;
            x[o + 3] += k.w * xf;
        }
    }
    float4* xnrow  = &g_xn[n * 16];
    float4* divrow = &g_div[n * 16];
#pragma unroll
    for (int q = 0; q < 16; q++) {
        xnrow[q]  = make_float4(x[4 * q], x[4 * q + 1], x[4 * q + 2], x[4 * q + 3]);
        divrow[q] = make_float4(0.f, 0.f, 0.f, 0.f);
    }
    float c0 = 0.f, c1 = 0.f, c2 = 0.f;
#pragma unroll
    for (int f = 0; f < 64; f++) {
        float4 kc = *(const float4*)&sCloseT[f * 4];
        c0 += kc.x * x[f]; c1 += kc.y * x[f]; c2 += kc.z * x[f];
    }
    g_coords[n] = make_float4(c0, c1, c2, 0.f);
    out_xx0[0 * NN + n] = c0;
    out_xx0[1 * NN + n] = c1;
    out_xx0[2 * NN + n] = c2;
    // y = KN[0] @ x  (chunked outputs)
#pragma unroll
    for (int oc = 0; oc < 4; oc++) {
        float acc[16];
#pragma unroll
        for (int q = 0; q < 16; q++) acc[q] = 0.f;
#pragma unroll
        for (int f = 0; f < 64; f++) {
            float xf = x[f];
#pragma unroll
            for (int q = 0; q < 16; q += 4) {
                float4 k = *(const float4*)&sKN0T[f * 64 + oc * 16 + q];
                acc[q]     += k.x * xf;
                acc[q + 1] += k.y * xf;
                acc[q + 2] += k.z * xf;
                acc[q + 3] += k.w * xf;
            }
        }
        float4* yrow = &g_y[n * 16 + oc * 4];
#pragma unroll
        for (int q = 0; q < 4; q++)
            yrow[q] = make_float4(acc[4 * q], acc[4 * q + 1], acc[4 * q + 2], acc[4 * q + 3]);
    }
}

// ---------------- E1: w + stats of a = w*(y_i - y_j) -----------------------
__global__ __launch_bounds__(256) void k_e1(
    const int* __restrict__ iInd, const int* __restrict__ jInd)
{
    __shared__ float sSum[64], sSq[64];
    int t = threadIdx.x;
    if (t < 64) { sSum[t] = 0.f; sSq[t] = 0.f; }
    __syncthreads();

    int lane   = t & 15;
    int group  = blockIdx.x * 16 + (t >> 4);
    int stride = gridDim.x * 16;
    float s0 = 0.f, s1 = 0.f, s2 = 0.f, s3 = 0.f;
    float q0 = 0.f, q1 = 0.f, q2 = 0.f, q3 = 0.f;

    for (int e = group; e < NE; e += stride) {
        int i = iInd[e], j = jInd[e];
        float4 ci = g_coords[i], cj = g_coords[j];
        float dx = ci.x - cj.x, dy = ci.y - cj.y, dz = ci.z - cj.z;
        float w = __expf(-10.f * (dx * dx + dy * dy + dz * dz));
        if (lane == 0) g_w[e] = w;
        float4 yi = g_y[i * 16 + lane];
        float4 yj = g_y[j * 16 + lane];
        float4 a = make_float4(w * (yi.x - yj.x), w * (yi.y - yj.y),
                               w * (yi.z - yj.z), w * (yi.w - yj.w));
        s0 += a.x; s1 += a.y; s2 += a.z; s3 += a.w;
        q0 += a.x * a.x; q1 += a.y * a.y; q2 += a.z * a.z; q3 += a.w * a.w;
    }
    int c = lane * 4;
    atomicAdd(&sSum[c], s0);     atomicAdd(&sSum[c + 1], s1);
    atomicAdd(&sSum[c + 2], s2); atomicAdd(&sSum[c + 3], s3);
    atomicAdd(&sSq[c], q0);      atomicAdd(&sSq[c + 1], q1);
    atomicAdd(&sSq[c + 2], q2);  atomicAdd(&sSq[c + 3], q3);
    __syncthreads();
    if (t < 64)       atomicAdd(&g_sum[t], (double)sSum[t]);
    else if (t < 128) atomicAdd(&g_sumsq[t - 64], (double)sSq[t - 64]);
}

// ---------------- E2 (layers 0,1): recompute a, normalize+relu, scatter ----
__global__ __launch_bounds__(256) void k_e2(
    const int* __restrict__ iInd, const int* __restrict__ jInd)
{
    int t    = threadIdx.x;
    int lane = t & 15;
    int c    = lane * 4;

    float mean[4], inv[4];
    const double invE = 1.0 / (double)NE;
#pragma unroll
    for (int d = 0; d < 4; d++) {
        double s  = g_sum[c + d];
        double sq = g_sumsq[c + d];
        double mu = s * invE;
        double var = sq * invE - mu * mu;
        mean[d] = (float)mu;
        inv[d]  = rsqrtf((float)var + 1e-5f);
    }

    int group  = blockIdx.x * 16 + (t >> 4);
    int stride = gridDim.x * 16;
    for (int e = group; e < NE; e += stride) {
        int i = iInd[e], j = jInd[e];
        float w = g_w[e];
        float4 yi = g_y[i * 16 + lane];
        float4 yj = g_y[j * 16 + lane];
        float4 a = make_float4(w * (yi.x - yj.x), w * (yi.y - yj.y),
                               w * (yi.z - yj.z), w * (yi.w - yj.w));
        float4 x;
        x.x = fmaxf(0.f, (a.x - mean[0]) * inv[0]);
        x.y = fmaxf(0.f, (a.y - mean[1]) * inv[1]);
        x.z = fmaxf(0.f, (a.z - mean[2]) * inv[2]);
        x.w = fmaxf(0.f, (a.w - mean[3]) * inv[3]);
        float4 wg = make_float4(w * x.x, w * x.y, w * x.z, w * x.w);
        red_add_v4(&g_div[i * 16 + lane], wg);
        red_add_v4(&g_div[j * 16 + lane],
                   make_float4(-wg.x, -wg.y, -wg.z, -wg.w));
    }
}

// ---------------- E2 last layer: thread-per-edge + fused xe_out ------------
__global__ __launch_bounds__(256) void k_e2_last(
    const int* __restrict__ iInd, const int* __restrict__ jInd,
    const float* __restrict__ KEclose,     // [16][64]
    float* __restrict__ out_xe)            // [16][NE]
{
    __shared__ float sKT[64 * 16];   // [c][k]
    __shared__ float sMean[64], sInv[64];
    int t = threadIdx.x;
    for (int idx = t; idx < 1024; idx += 256) {
        int k = idx / 64, c = idx % 64;
        sKT[c * 16 + k] = KEclose[idx];
    }
    if (t < 64) {
        const double invE = 1.0 / (double)NE;
        double s  = g_sum[t];
        double sq = g_sumsq[t];
        double mu = s * invE;
        double var = sq * invE - mu * mu;
        sMean[t] = (float)mu;
        sInv[t]  = rsqrtf((float)var + 1e-5f);
    }
    __syncthreads();

    int e = blockIdx.x * 256 + t;
    if (e >= NE) return;
    int i = iInd[e], j = jInd[e];
    float w = g_w[e];

    float acc[16];
#pragma unroll
    for (int k = 0; k < 16; k++) acc[k] = 0.f;

#pragma unroll
    for (int q = 0; q < 16; q++) {
        float4 yi = g_y[i * 16 + q];
        float4 yj = g_y[j * 16 + q];
        float4 mn = *(const float4*)&sMean[4 * q];
        float4 iv = *(const float4*)&sInv[4 * q];
        float4 x;
        x.x = fmaxf(0.f, (w * (yi.x - yj.x) - mn.x) * iv.x);
        x.y = fmaxf(0.f, (w * (yi.y - yj.y) - mn.y) * iv.y);
        x.z = fmaxf(0.f, (w * (yi.z - yj.z) - mn.z) * iv.z);
        x.w = fmaxf(0.f, (w * (yi.w - yj.w) - mn.w) * iv.w);
        float4 wg = make_float4(w * x.x, w * x.y, w * x.z, w * x.w);
        red_add_v4(&g_div[i * 16 + q], wg);
        red_add_v4(&g_div[j * 16 + q],
                   make_float4(-wg.x, -wg.y, -wg.z, -wg.w));
        float xs[4] = {x.x, x.y, x.z, x.w};
#pragma unroll
        for (int dd = 0; dd < 4; dd++) {
            float xc = xs[dd];
            int c = 4 * q + dd;
#pragma unroll
            for (int kq = 0; kq < 4; kq++) {
                float4 kk = *(const float4*)&sKT[c * 16 + kq * 4];
                acc[kq * 4]     += kk.x * xc;
                acc[kq * 4 + 1] += kk.y * xc;
                acc[kq * 4 + 2] += kk.z * xc;
                acc[kq * 4 + 3] += kk.w * xc;
            }
        }
    }
#pragma unroll
    for (int k = 0; k < 16; k++) out_xe[k * NE + e] = acc[k];
}

// ---------------- Node update v3: 2 nodes x 32 channels per thread ---------
// 128 threads, 128 nodes/block, grid 391 (same warps as the proven R3
// kernel). Thread (nl = t>>1, h = t&1) handles nodes base+nl and base+nl+64,
// channels [32h, 32h+32). Every 16B K smem read feeds 8 FMAs (2 B/FMA, half
// of R3). x is staged in a smem buffer sX (rows padded to 68 floats) so the
// y matvec needs no shfl and no global x re-reads. Dynamic smem:
// sK(16K) + sKnT(16K) + sX(34K) = 66KB. FP accumulation order identical to
// R3 in all matvecs -> bit-identical outputs.
#define SX_PITCH 68
__global__ void __launch_bounds__(128) k_node(
    const float* __restrict__ KNi,     // KN[i] [e][c]
    const float* __restrict__ KNnext,  // KN[i+1] or nullptr
    const float* __restrict__ KNclose,
    float* __restrict__ out_xx,        // XX[i+1]: [3][NN]
    float* __restrict__ out_xn,        // final xn out or nullptr
    int zero_sums)
{
    extern __shared__ float dyn[];
    float* sK   = dyn;               // [e][c], 4096
    float* sKnT = dyn + 4096;        // [f][o], 4096
    float* sX   = dyn + 8192;        // 128 rows x 68
    __shared__ float sCloseT[256];   // [f][c], c padded to 4

    int t = threadIdx.x;
    for (int idx = t; idx < 4096; idx += 128) sK[idx] = KNi[idx];
    if (KNnext) {
        for (int idx = t; idx < 4096; idx += 128) {
            int o = idx / 64, f = idx % 64;
            sKnT[f * 64 + o] = KNnext[idx];
        }
    }
    for (int idx = t; idx < 256; idx += 128) {
        int f = idx / 4, cc = idx % 4;
        sCloseT[idx] = (cc < 3) ? KNclose[cc * 64 + f] : 0.f;
    }
    if (zero_sums && blockIdx.x == 0 && t < 64) { g_sum[t] = 0.0; g_sumsq[t] = 0.0; }
    __syncthreads();

    int nl = t >> 1, h = t & 1;
    int cb = 32 * h;
    int nA = blockIdx.x * 128 + nl;
    int nB = nA + 64;
    bool vA = nA < NN, vB = nB < NN;
    const float4 z4 = make_float4(0.f, 0.f, 0.f, 0.f);

    // ---- phase 1: acc{A,B}[c] = sum_e K[e][c]*d{A,B}[e], K reused 2x ----
    float accA[32], accB[32];
#pragma unroll
    for (int c = 0; c < 32; c++) { accA[c] = 0.f; accB[c] = 0.f; }
#pragma unroll
    for (int q = 0; q < 16; q++) {
        float4 dvA = vA ? g_div[(size_t)nA * 16 + q] : z4;
        float4 dvB = vB ? g_div[(size_t)nB * 16 + q] : z4;
        float dsA[4] = {dvA.x, dvA.y, dvA.z, dvA.w};
        float dsB[4] = {dvB.x, dvB.y, dvB.z, dvB.w};
#pragma unroll
        for (int ee = 0; ee < 4; ee++) {
            float deA = dsA[ee], deB = dsB[ee];
            const float* krow = &sK[(4 * q + ee) * 64 + cb];
#pragma unroll
            for (int c = 0; c < 32; c += 4) {
                float4 k = *(const float4*)&krow[c];
                accA[c]     += k.x * deA;  accB[c]     += k.x * deB;
                accA[c + 1] += k.y * deA;  accB[c + 1] += k.y * deB;
                accA[c + 2] += k.z * deA;  accB[c + 2] += k.z * deB;
                accA[c + 3] += k.w * deA;  accB[c + 3] += k.w * deB;
            }
        }
    }
    // zero div for next layer; the pair (same warp) finished reading the rows
    __syncwarp();
    if (vA) {
#pragma unroll
        for (int q = 0; q < 8; q++)
            g_div[(size_t)nA * 16 + 8 * h + q] = z4;
    }
    if (vB) {
#pragma unroll
        for (int q = 0; q < 8; q++)
            g_div[(size_t)nB * 16 + 8 * h + q] = z4;
    }

    // ---- phase 2: x = xn - H*acc; write g_xn and stage into sX ----
    if (vA) {
#pragma unroll
        for (int q = 0; q < 8; q++) {
            float4 xv = g_xn[(size_t)nA * 16 + 8 * h + q];
            xv.x -= H_STEP * accA[4 * q];
            xv.y -= H_STEP * accA[4 * q + 1];
            xv.z -= H_STEP * accA[4 * q + 2];
            xv.w -= H_STEP * accA[4 * q + 3];
            g_xn[(size_t)nA * 16 + 8 * h + q] = xv;
            *(float4*)&sX[nl * SX_PITCH + cb + 4 * q] = xv;
        }
    }
    if (vB) {
#pragma unroll
        for (int q = 0; q < 8; q++) {
            float4 xv = g_xn[(size_t)nB * 16 + 8 * h + q];
            xv.x -= H_STEP * accB[4 * q];
            xv.y -= H_STEP * accB[4 * q + 1];
            xv.z -= H_STEP * accB[4 * q + 2];
            xv.w -= H_STEP * accB[4 * q + 3];
            g_xn[(size_t)nB * 16 + 8 * h + q] = xv;
            *(float4*)&sX[(nl + 64) * SX_PITCH + cb + 4 * q] = xv;
        }
    }
    __syncthreads();

    // ---- coords: h==0 thread handles both of its nodes from sX ----
    if (h == 0) {
#pragma unroll 1
        for (int s = 0; s < 2; s++) {
            int n = s ? nB : nA;
            bool v = s ? vB : vA;
            if (!v) continue;
            const float* xr = &sX[(nl + 64 * s) * SX_PITCH];
            float c0 = 0.f, c1 = 0.f, c2 = 0.f;
#pragma unroll
            for (int f = 0; f < 64; f++) {
                float4 kc = *(const float4*)&sCloseT[f * 4];
                float xf = xr[f];
                c0 += kc.x * xf; c1 += kc.y * xf; c2 += kc.z * xf;
            }
            g_coords[n] = make_float4(c0, c1, c2, 0.f);
            out_xx[0 * NN + n] = c0;
            out_xx[1 * NN + n] = c1;
            out_xx[2 * NN + n] = c2;
            if (out_xn) {
                out_xn[0 * NN + n] = c0;
                out_xn[1 * NN + n] = c1;
                out_xn[2 * NN + n] = c2;
            }
        }
    }

    // ---- y = KNnext @ x: own 32 outputs x 2 nodes; x from sX, K reused 2x -
    if (KNnext) {
        float yA[32], yB[32];
#pragma unroll
        for (int c = 0; c < 32; c++) { yA[c] = 0.f; yB[c] = 0.f; }
        const float* xrA = &sX[nl * SX_PITCH];
        const float* xrB = &sX[(nl + 64) * SX_PITCH];
#pragma unroll
        for (int f = 0; f < 64; f++) {
            float xa = xrA[f];
            float xb = xrB[f];
            const float* kcol = &sKnT[f * 64 + cb];
#pragma unroll
            for (int c = 0; c < 32; c += 4) {
                float4 k = *(const float4*)&kcol[c];
                yA[c]     += k.x * xa;  yB[c]     += k.x * xb;
                yA[c + 1] += k.y * xa;  yB[c + 1] += k.y * xb;
                yA[c + 2] += k.z * xa;  yB[c + 2] += k.z * xb;
                yA[c + 3] += k.w * xa;  yB[c + 3] += k.w * xb;
            }
        }
        if (vA) {
#pragma unroll
            for (int q = 0; q < 8; q++)
                g_y[(size_t)nA * 16 + 8 * h + q] =
                    make_float4(yA[4 * q], yA[4 * q + 1],
                                yA[4 * q + 2], yA[4 * q + 3]);
        }
        if (vB) {
#pragma unroll
            for (int q = 0; q < 8; q++)
                g_y[(size_t)nB * 16 + 8 * h + q] =
                    make_float4(yB[4 * q], yB[4 * q + 1],
                                yB[4 * q + 2], yB[4 * q + 3]);
        }
    }
}

// ---------------- launcher -------------------------------------------------
extern "C" void kernel_launch(void* const* d_in, const int* in_sizes, int n_in,
                              void* d_out, int out_size)
{
    const float* xn_in   = (const float*)d_in[0];
    // d_in[1] = xe input: dead (overwritten before first read in reference)
    const int*   iInd    = (const int*)d_in[2];
    const int*   jInd    = (const int*)d_in[3];
    const float* KNopen  = (const float*)d_in[4];
    // d_in[5] = KEopen: dead
    const float* KNclose = (const float*)d_in[6];
    const float* KEclose = (const float*)d_in[7];
    const float* KN      = (const float*)d_in[8];

    float* out    = (float*)d_out;
    float* out_xn = out;                       // [3][NN]
    float* out_xe = out + 3 * NN;              // [16][NE]
    float* out_XX = out + 3 * NN + 16 * NE;    // [4][3][NN]

    const int dynBytes = (4096 + 4096 + 128 * SX_PITCH) * 4;   // 67584
    // Attribute set is not a stream op; safe under graph capture. Idempotent.
    cudaFuncSetAttribute(k_node, cudaFuncAttributeMaxDynamicSharedMemorySize,
                         dynBytes);

    int nb_n  = (NN + 127) / 128;
    int nb_el = (NE + 255) / 256;
    const int GE = 1184;

    k_n0<<<nb_n, 128>>>(xn_in, KNopen, KNclose, KN, out_XX);
    for (int i = 0; i < 3; i++) {
        k_e1<<<GE, 256>>>(iInd, jInd);
        if (i < 2) k_e2<<<GE, 256>>>(iInd, jInd);
        else       k_e2_last<<<nb_el, 256>>>(iInd, jInd, KEclose, out_xe);
        const float* KNi = KN + i * 4096;
        const float* KNn = (i < 2) ? (KN + (i + 1) * 4096) : nullptr;
        float* xx  = out_XX + (size_t)(i + 1) * 3 * NN;
        float* oxn = (i == 2) ? out_xn : nullptr;
        k_node<<<nb_n, 128, dynBytes>>>(KNi, KNn, KNclose, xx, oxn,
                                        (i < 2) ? 1 : 0);
    }
}